// round 2
// baseline (speedup 1.0000x reference)
#include <cuda_runtime.h>

#define IR 1771          // sum_{l=0}^{10} (2l+1)^2
#define FIO 4096         // f_in * f_out
#define PSI_ROW_STRIDE (64 * IR)   // stride of i-index in psi (i,o) rows: 64*IR

// 29 MB scratch for psi = (f_in, f_out, IRREP_DIM)
__device__ float g_psi[64 * 64 * IR];

// per-l tables (compile-time constants for LMAX=10)
__constant__ int c_off[11] = {0, 1, 10, 35, 84, 165, 286, 455, 680, 969, 1330};
__constant__ int c_cum[12] = {0, 4, 40, 140, 336, 660, 1144, 1820, 2720, 3876, 5320, 7084};

// ---------------------------------------------------------------------------
// Kernel A: psi[(i*64+o), m] = (1/sqrt(512)) * sum_n w[(i*64+o)*512 + n] * D[n*IR + m]
// Tiled 64x64x16 fp32 GEMM. M=4096, N=1771 (bounds-checked), K=512.
// ---------------------------------------------------------------------------
__global__ __launch_bounds__(256) void psi_kernel(const float* __restrict__ D,
                                                  const float* __restrict__ w) {
    __shared__ float sA[16][68];   // w tile, stored transposed, padded (272B rows, 16B-aligned)
    __shared__ float sB[16][64];   // D tile

    const int tid = threadIdx.x;
    const int pBase = blockIdx.y << 6;
    const int nBase = blockIdx.x << 6;
    const int tx = tid & 15, ty = tid >> 4;

    // A loader: 16 k-cols x 16 rows per pass (coalesced 64B rows of w)
    const int kcA = tid & 15, rA0 = tid >> 4;
    // B loader: 64 cols x 4 k-rows per pass (fully coalesced rows of D)
    const int cB = tid & 63, krB0 = tid >> 6;
    const int mcol = nBase + cB;

    float acc[4][4] = {};

    for (int kt = 0; kt < 512; kt += 16) {
#pragma unroll
        for (int q = 0; q < 4; ++q) {
            int r = rA0 + (q << 4);
            sA[kcA][r] = w[(pBase + r) * 512 + kt + kcA];
        }
#pragma unroll
        for (int q = 0; q < 4; ++q) {
            int kr = krB0 + (q << 2);
            sB[kr][cB] = (mcol < IR) ? D[(kt + kr) * IR + mcol] : 0.0f;
        }
        __syncthreads();
#pragma unroll
        for (int k = 0; k < 16; ++k) {
            float4 a4 = *(const float4*)&sA[k][ty << 2];
            float4 b4 = *(const float4*)&sB[k][tx << 2];
            float av[4] = {a4.x, a4.y, a4.z, a4.w};
            float bv[4] = {b4.x, b4.y, b4.z, b4.w};
#pragma unroll
            for (int r = 0; r < 4; ++r)
#pragma unroll
                for (int j = 0; j < 4; ++j)
                    acc[r][j] = fmaf(av[r], bv[j], acc[r][j]);
        }
        __syncthreads();
    }

    const float scale = 0.04419417382415922f;  // 1/sqrt(512)
#pragma unroll
    for (int r = 0; r < 4; ++r) {
        int p = pBase + (ty << 2) + r;
#pragma unroll
        for (int j = 0; j < 4; ++j) {
            int m = nBase + (tx << 2) + j;
            if (m < IR) g_psi[p * IR + m] = acc[r][j] * scale;
        }
    }
}

// ---------------------------------------------------------------------------
// Kernel B: per-l GEMM. For degree l (d=2l+1):
//   C[(o,v),(b,m)] = alpha_l * sum_{(i,u)} psi[(i,o),(u,v)] * x[b,i,(u,m)]
// M=64d, N=256d, K=64d -> all tile dims exact (64x64x16), no bounds checks.
// 7084 blocks total, l found from c_cum.
// ---------------------------------------------------------------------------
__global__ __launch_bounds__(256) void so3_kernel(const float* __restrict__ x,
                                                  float* __restrict__ out) {
    const int bx = blockIdx.x;
    int l = 0;
#pragma unroll
    for (int j = 1; j < 11; ++j) l += (bx >= c_cum[j]);

    const int d = 2 * l + 1;
    const int off = c_off[l];
    const float invd = 1.0f / (float)d;
    const int t = bx - c_cum[l];
    const int tiles_n = d << 2;            // N/64 = 4d
    const int tm = t / tiles_n;
    const int tn = t - tm * tiles_n;
    const int mBase = tm << 6;
    const int nBase = tn << 6;
    const int K = d << 6;
    const float alpha = rsqrtf((float)(d << 6));   // 1/sqrt(64*d)

    const int tid = threadIdx.x;
    const int cload = tid & 63;
    const int kr0 = tid >> 6;
    const int tx = tid & 15, ty = tid >> 4;

    // Fixed per-thread column decompositions (float-reciprocal division by d;
    // bias 0.01 safe: abs err <= 5375*2^-23 + rounding << 1/21 gap)
    const int mmA = mBase + cload;                       // (o, v)
    const int oA = (int)((float)mmA * invd + 0.01f);
    const int vA = mmA - oA * d;
    const int ccB = nBase + cload;                       // (b, m)
    const int bB = (int)((float)ccB * invd + 0.01f);
    const int mB = ccB - bB * d;

    const int aColOff = oA * IR + off + vA;              // + i*64*IR + u*d
    const int bColOff = bB * (64 * IR) + off + mB;       // + i*IR    + u*d

    __shared__ float sA[16][64];
    __shared__ float sB[16][64];
    float acc[4][4] = {};

    for (int kt = 0; kt < K; kt += 16) {
#pragma unroll
        for (int q = 0; q < 4; ++q) {
            int kr = kr0 + (q << 2);
            int kk = kt + kr;
            int i = (int)((float)kk * invd + 0.01f);
            int ud = (kk - i * d) * d;
            sA[kr][cload] = g_psi[i * PSI_ROW_STRIDE + ud + aColOff];
            sB[kr][cload] = x[i * IR + ud + bColOff];
        }
        __syncthreads();
#pragma unroll
        for (int k = 0; k < 16; ++k) {
            float4 a4 = *(const float4*)&sA[k][ty << 2];
            float4 b4 = *(const float4*)&sB[k][tx << 2];
            float av[4] = {a4.x, a4.y, a4.z, a4.w};
            float bv[4] = {b4.x, b4.y, b4.z, b4.w};
#pragma unroll
            for (int r = 0; r < 4; ++r)
#pragma unroll
                for (int j = 0; j < 4; ++j)
                    acc[r][j] = fmaf(av[r], bv[j], acc[r][j]);
        }
        __syncthreads();
    }

    // Epilogue: out[b, o, off + v*d + m] = alpha * acc
#pragma unroll
    for (int r = 0; r < 4; ++r) {
        int mm = mBase + (ty << 2) + r;
        int o = (int)((float)mm * invd + 0.01f);
        int v = mm - o * d;
        int rowOff = o * IR + off + v * d;
#pragma unroll
        for (int j = 0; j < 4; ++j) {
            int cc = nBase + (tx << 2) + j;
            int b = (int)((float)cc * invd + 0.01f);
            int m = cc - b * d;
            out[b * (64 * IR) + rowOff + m] = acc[r][j] * alpha;
        }
    }
}

// ---------------------------------------------------------------------------
extern "C" void kernel_launch(void* const* d_in, const int* in_sizes, int n_in,
                              void* d_out, int out_size) {
    const float *x = nullptr, *D = nullptr, *w = nullptr;
    for (int i = 0; i < n_in; ++i) {
        int s = in_sizes[i];
        if (s == 256 * 64 * IR) x = (const float*)d_in[i];          // 29016064
        else if (s == 512 * IR) D = (const float*)d_in[i];          // 906752
        else if (s == 64 * 64 * 512) w = (const float*)d_in[i];     // 2097152
    }

    psi_kernel<<<dim3((IR + 63) / 64, FIO / 64), 256>>>(D, w);
    so3_kernel<<<7084, 256>>>(x, (float*)d_out);
}

// round 4
// speedup vs baseline: 1.8077x; 1.8077x over previous
#include <cuda_runtime.h>
#include <cstdint>

#define IR 1771
#define BSTRIDE (64 * IR)
#define SCALE_PSI 0.04419417382415922f   // 1/sqrt(512)

// 29 MB scratch: psi[(i*64+o)*IR + m]
__device__ float g_psi[64 * 64 * IR];

// cumulative 2*d^2 tile counts for so3 grid (3542 total)
__constant__ int c_cum2[12] = {0, 2, 20, 70, 168, 330, 572, 910, 1360, 1938, 2660, 3542};
__constant__ int c_off[11]  = {0, 1, 10, 35, 84, 165, 286, 455, 680, 969, 1330};
__constant__ float c_invd[11] = {1.0f, 1.0f/3.0f, 0.2f, 1.0f/7.0f, 1.0f/9.0f, 1.0f/11.0f,
                                 1.0f/13.0f, 1.0f/15.0f, 1.0f/17.0f, 1.0f/19.0f, 1.0f/21.0f};
__constant__ float c_alpha[11] = {0.125f, 0.072168784f, 0.055901699f, 0.047245559f,
                                  0.041666667f, 0.037688918f, 0.034668700f, 0.032274861f,
                                  0.030316953f, 0.028676967f, 0.027277236f};

__device__ __forceinline__ uint32_t f2tf(float v) {   // RN round to tf32
    uint32_t r; asm("cvt.rna.tf32.f32 %0, %1;" : "=r"(r) : "f"(v)); return r;
}
__device__ __forceinline__ void mma8(float* c, const uint32_t* a, const uint32_t* b) {
    asm volatile(
        "mma.sync.aligned.m16n8k8.row.col.f32.tf32.tf32.f32 "
        "{%0,%1,%2,%3}, {%4,%5,%6,%7}, {%8,%9}, {%0,%1,%2,%3};"
        : "+f"(c[0]), "+f"(c[1]), "+f"(c[2]), "+f"(c[3])
        : "r"(a[0]), "r"(a[1]), "r"(a[2]), "r"(a[3]), "r"(b[0]), "r"(b[1]));
}

#define SA 132   // so3 A smem stride ([k][m], m=128 + 4 pad) — conflict-free STS & frags
#define SP 133   // psi A smem stride ([k][p]) — 5 coprime 32: conflict-free STS
#define SB 68    // B smem stride ([k][n], n=64 + 4 pad)

// ===========================================================================
// psi kernel: psi[p, m] = (1/sqrt(512)) * sum_n w[p*512+n] * D[n*IR+m]
// Block tile 128(p) x 64(m), K=512 in 16 chunks of 32. Warp tile 32x32.
// ===========================================================================
__global__ __launch_bounds__(256, 2) void psi_mm(const float* __restrict__ Dg,
                                                 const float* __restrict__ wg) {
    __shared__ uint32_t sAs[32 * SP];
    __shared__ uint32_t sBs[32 * SB];

    const int tid = threadIdx.x;
    const int pBase = blockIdx.y << 7;
    const int nB = blockIdx.x << 6;

    // A loader (w): lane = k (coalesced rows of w); p = p0 + 8q
    const int kA = tid & 31, p0 = tid >> 5;
    // B loader (D): lane = m (coalesced rows of D); k = kB0 + 4q
    const int mBl = tid & 63, kB0 = tid >> 6;
    const int mCol = nB + mBl;

    const int lane = tid & 31, wid = tid >> 5;
    const int wm = wid >> 1, wn = wid & 1;
    const int gid = lane >> 2, tig = lane & 3;
    const int mrow = (wm << 5) + gid;
    const int ncol = (wn << 5) + gid;

    float acc[2][4][4] = {};
    float av[16], bv[8];

    // preload chunk 0
#pragma unroll
    for (int q = 0; q < 16; ++q) av[q] = wg[(pBase + p0 + (q << 3)) * 512 + kA];
#pragma unroll
    for (int q = 0; q < 8; ++q)
        bv[q] = (mCol < IR) ? Dg[(kB0 + (q << 2)) * IR + mCol] : 0.0f;

    for (int ck = 0; ck < 16; ++ck) {
        __syncthreads();
#pragma unroll
        for (int q = 0; q < 16; ++q) sAs[kA * SP + p0 + (q << 3)] = f2tf(av[q]);
#pragma unroll
        for (int q = 0; q < 8; ++q) sBs[(kB0 + (q << 2)) * SB + mBl] = f2tf(bv[q]);
        __syncthreads();

        if (ck < 15) {
            const int kN = (ck + 1) << 5;
#pragma unroll
            for (int q = 0; q < 16; ++q)
                av[q] = wg[(pBase + p0 + (q << 3)) * 512 + kN + kA];
#pragma unroll
            for (int q = 0; q < 8; ++q)
                bv[q] = (mCol < IR) ? Dg[(kN + kB0 + (q << 2)) * IR + mCol] : 0.0f;
        }

#pragma unroll
        for (int ks = 0; ks < 4; ++ks) {
            const int k0 = ks << 3;
            uint32_t a[2][4], bf[4][2];
#pragma unroll
            for (int mf = 0; mf < 2; ++mf) {
                int mb = mrow + (mf << 4);
                a[mf][0] = sAs[(k0 + tig) * SP + mb];
                a[mf][1] = sAs[(k0 + tig) * SP + mb + 8];
                a[mf][2] = sAs[(k0 + tig + 4) * SP + mb];
                a[mf][3] = sAs[(k0 + tig + 4) * SP + mb + 8];
            }
#pragma unroll
            for (int nf = 0; nf < 4; ++nf) {
                bf[nf][0] = sBs[(k0 + tig) * SB + ncol + (nf << 3)];
                bf[nf][1] = sBs[(k0 + tig + 4) * SB + ncol + (nf << 3)];
            }
#pragma unroll
            for (int mf = 0; mf < 2; ++mf)
#pragma unroll
                for (int nf = 0; nf < 4; ++nf) mma8(acc[mf][nf], a[mf], bf[nf]);
        }
    }

    // epilogue
#pragma unroll
    for (int mf = 0; mf < 2; ++mf)
#pragma unroll
        for (int i = 0; i < 2; ++i) {
            int p = pBase + mrow + (mf << 4) + (i << 3);
#pragma unroll
            for (int nf = 0; nf < 4; ++nf)
#pragma unroll
                for (int j = 0; j < 2; ++j) {
                    int m = nB + (wn << 5) + (nf << 3) + (tig << 1) + j;
                    if (m < IR)
                        g_psi[p * IR + m] = acc[mf][nf][(i << 1) + j] * SCALE_PSI;
                }
        }
}

// ===========================================================================
// so3 kernel: per degree l (d=2l+1):
//   C[(b,m), (o,v)] = alpha_l * sum_{(i,u)} x[b,i,off+u*d+m] * psi[(i,o), off+u*d+v]
// Block tile M=128 over bm=b*d+m, N=64 over ov=o*d+v, K=64d in 2d chunks of 32.
// 2d^2 tiles per l -> 3542 blocks.
// ===========================================================================
__global__ __launch_bounds__(256, 2) void so3_mm(const float* __restrict__ xg,
                                                 float* __restrict__ outg) {
    __shared__ uint32_t sAs[32 * SA];
    __shared__ uint32_t sBs[32 * SB];

    const int tid = threadIdx.x;
    const int bx = blockIdx.x;
    int l = 0;
#pragma unroll
    for (int j = 1; j < 11; ++j) l += (bx >= c_cum2[j]);
    const int d = 2 * l + 1;
    const int off = c_off[l];
    const float invd = c_invd[l];
    const int t = bx - c_cum2[l];
    const int tile_m = (int)((float)t * invd + 0.01f);  // t / d
    const int tile_n = t - tile_m * d;
    const int mBase = tile_m << 7;
    const int nBase = tile_n << 6;
    const int nChunks = d << 1;

    // A loader (x): fixed row rA over bm; k = cA0 + 2q
    const int rA = tid & 127, cA0 = tid >> 7;
    const int bmA = mBase + rA;
    const int bA = (int)((float)bmA * invd + 0.01f);
    const int mA = bmA - bA * d;
    const int aRow = bA * BSTRIDE + off + mA;
    // B loader (psi): fixed row rB over ov; k = kB0 + 4q
    const int rB = tid & 63, kB0 = tid >> 6;
    const int ovB = nBase + rB;
    const int oB = (int)((float)ovB * invd + 0.01f);
    const int vB = ovB - oB * d;
    const int bRow = oB * IR + off + vB;

    const int lane = tid & 31, wid = tid >> 5;
    const int wm = wid >> 1, wn = wid & 1;
    const int gid = lane >> 2, tig = lane & 3;
    const int mrow = (wm << 5) + gid;
    const int ncol = (wn << 5) + gid;

    float acc[2][4][4] = {};
    float av[16], bv[8];

    // preload chunk 0
#pragma unroll
    for (int q = 0; q < 16; ++q) {
        int k = cA0 + (q << 1);
        int i = (int)((float)k * invd + 0.01f);
        av[q] = xg[aRow + i * IR + (k - i * d) * d];
    }
#pragma unroll
    for (int q = 0; q < 8; ++q) {
        int k = kB0 + (q << 2);
        int i = (int)((float)k * invd + 0.01f);
        bv[q] = g_psi[bRow + i * BSTRIDE + (k - i * d) * d];
    }

    for (int ck = 0; ck < nChunks; ++ck) {
        __syncthreads();
#pragma unroll
        for (int q = 0; q < 16; ++q) sAs[(cA0 + (q << 1)) * SA + rA] = f2tf(av[q]);
#pragma unroll
        for (int q = 0; q < 8; ++q) sBs[(kB0 + (q << 2)) * SB + rB] = f2tf(bv[q]);
        __syncthreads();

        if (ck + 1 < nChunks) {
            const int kN = (ck + 1) << 5;
#pragma unroll
            for (int q = 0; q < 16; ++q) {
                int k = kN + cA0 + (q << 1);
                int i = (int)((float)k * invd + 0.01f);
                av[q] = xg[aRow + i * IR + (k - i * d) * d];
            }
#pragma unroll
            for (int q = 0; q < 8; ++q) {
                int k = kN + kB0 + (q << 2);
                int i = (int)((float)k * invd + 0.01f);
                bv[q] = g_psi[bRow + i * BSTRIDE + (k - i * d) * d];
            }
        }

#pragma unroll
        for (int ks = 0; ks < 4; ++ks) {
            const int k0 = ks << 3;
            uint32_t a[2][4], bf[4][2];
#pragma unroll
            for (int mf = 0; mf < 2; ++mf) {
                int mb = mrow + (mf << 4);
                a[mf][0] = sAs[(k0 + tig) * SA + mb];
                a[mf][1] = sAs[(k0 + tig) * SA + mb + 8];
                a[mf][2] = sAs[(k0 + tig + 4) * SA + mb];
                a[mf][3] = sAs[(k0 + tig + 4) * SA + mb + 8];
            }
#pragma unroll
            for (int nf = 0; nf < 4; ++nf) {
                bf[nf][0] = sBs[(k0 + tig) * SB + ncol + (nf << 3)];
                bf[nf][1] = sBs[(k0 + tig + 4) * SB + ncol + (nf << 3)];
            }
#pragma unroll
            for (int mf = 0; mf < 2; ++mf)
#pragma unroll
                for (int nf = 0; nf < 4; ++nf) mma8(acc[mf][nf], a[mf], bf[nf]);
        }
    }

    // epilogue: out[b*BSTRIDE + o*IR + off + v*d + m] = alpha * acc
    const float alpha = c_alpha[l];
#pragma unroll
    for (int mf = 0; mf < 2; ++mf)
#pragma unroll
        for (int i = 0; i < 2; ++i) {
            int bm = mBase + mrow + (mf << 4) + (i << 3);
            int b = (int)((float)bm * invd + 0.01f);
            int m = bm - b * d;
            float* orow = outg + b * BSTRIDE + off + m;
#pragma unroll
            for (int nf = 0; nf < 4; ++nf)
#pragma unroll
                for (int j = 0; j < 2; ++j) {
                    int ov = nBase + (wn << 5) + (nf << 3) + (tig << 1) + j;
                    int o = (int)((float)ov * invd + 0.01f);
                    int v = ov - o * d;
                    orow[o * IR + v * d] = acc[mf][nf][(i << 1) + j] * alpha;
                }
        }
}

// ---------------------------------------------------------------------------
extern "C" void kernel_launch(void* const* d_in, const int* in_sizes, int n_in,
                              void* d_out, int out_size) {
    const float *x = nullptr, *D = nullptr, *w = nullptr;
    for (int i = 0; i < n_in; ++i) {
        int s = in_sizes[i];
        if (s == 256 * 64 * IR) x = (const float*)d_in[i];
        else if (s == 512 * IR) D = (const float*)d_in[i];
        else if (s == 64 * 64 * 512) w = (const float*)d_in[i];
    }

    psi_mm<<<dim3(28, 32), 256>>>(D, w);
    so3_mm<<<3542, 256>>>(x, (float*)d_out);
}

// round 5
// speedup vs baseline: 2.9492x; 1.6314x over previous
#include <cuda_runtime.h>
#include <cstdint>

#define IR 1771
#define BSTRIDE (64 * IR)
#define SCALE_PSI 0.04419417382415922f   // 1/sqrt(512)

// ---------------- device scratch (all zero-initialized .bss) ----------------
__device__ float g_wT[64 * 64 * 512];     // rna-rounded w  [p=4096][k=512]
__device__ float g_DT[1792 * 512];        // rna D^T [m(pad 1792)][n=512]
__device__ float g_psiT[7344128];         // per-l [ov][k] rna (+86016 pad)
__device__ float g_xT[29016064];          // per-l [bm][k] rna

__constant__ int c_off[11]  = {0, 1, 10, 35, 84, 165, 286, 455, 680, 969, 1330};
__constant__ int c_PT[11]   = {0, 8192, 45056, 147456, 348160, 679936, 1175552,
                               1867776, 2789376, 3973120, 5451776};
__constant__ int c_XT[11]   = {0, 16384, 163840, 573440, 1376256, 2703360, 4685824,
                               7454720, 11141120, 15876096, 21790720};
__constant__ int c_tcum[12] = {0, 2, 14, 44, 100, 190, 322, 504, 744, 1050, 1430, 1892};
__constant__ float c_invd[11]  = {1.0f, 1.0f/3.0f, 0.2f, 1.0f/7.0f, 1.0f/9.0f, 1.0f/11.0f,
                                  1.0f/13.0f, 1.0f/15.0f, 1.0f/17.0f, 1.0f/19.0f, 1.0f/21.0f};
__constant__ float c_inv2d[11] = {0.5f, 1.0f/6.0f, 0.1f, 1.0f/14.0f, 1.0f/18.0f, 1.0f/22.0f,
                                  1.0f/26.0f, 1.0f/30.0f, 1.0f/34.0f, 1.0f/38.0f, 1.0f/42.0f};
__constant__ float c_alpha[11] = {0.125f, 0.072168784f, 0.055901699f, 0.047245559f,
                                  0.041666667f, 0.037688918f, 0.034668700f, 0.032274861f,
                                  0.030316953f, 0.028676967f, 0.027277236f};

// ---------------------------------------------------------------- helpers
__device__ __forceinline__ uint32_t s2u(const void* p) {
    uint32_t a;
    asm("{ .reg .u64 t; cvta.to.shared.u64 t, %1; cvt.u32.u64 %0, t; }" : "=r"(a) : "l"(p));
    return a;
}
__device__ __forceinline__ uint32_t f2tf(float v) {   // RN round to tf32
    uint32_t r; asm("cvt.rna.tf32.f32 %0, %1;" : "=r"(r) : "f"(v)); return r;
}
__device__ __forceinline__ void mma8(float* c, const uint32_t* a, const uint32_t* b) {
    asm volatile(
        "mma.sync.aligned.m16n8k8.row.col.f32.tf32.tf32.f32 "
        "{%0,%1,%2,%3}, {%4,%5,%6,%7}, {%8,%9}, {%0,%1,%2,%3};"
        : "+f"(c[0]), "+f"(c[1]), "+f"(c[2]), "+f"(c[3])
        : "r"(a[0]), "r"(a[1]), "r"(a[2]), "r"(a[3]), "r"(b[0]), "r"(b[1]));
}
__device__ __forceinline__ void ldsm4(uint32_t* r, uint32_t addr) {
    asm volatile("ldmatrix.sync.aligned.m8n8.x4.shared.b16 {%0,%1,%2,%3}, [%4];"
                 : "=r"(r[0]), "=r"(r[1]), "=r"(r[2]), "=r"(r[3]) : "r"(addr));
}
__device__ __forceinline__ void cpa16(uint32_t dst, const float* src) {
    asm volatile("cp.async.cg.shared.global [%0], [%1], 16;" :: "r"(dst), "l"(src));
}
#define CP_COMMIT asm volatile("cp.async.commit_group;" ::: "memory")
#define CP_WAIT1  asm volatile("cp.async.wait_group 1;" ::: "memory")

// ===========================================================================
// Dense GEMM core: C[128,128] += A[128,K] * B[128,K]^T, both k-contiguous tf32.
// 8 warps (2m x 4n), warp tile 64x32, K-chunk 32, 3-stage cp.async pipeline,
// ldmatrix.x4 fragments, XOR-swizzled smem (8x16B segs per 128B row).
// ===========================================================================
__device__ __forceinline__ void gemm_core(const float* __restrict__ A,
                                          const float* __restrict__ B,
                                          int K, uint32_t smem,
                                          float (&acc)[4][4][4]) {
    const int tid = threadIdx.x;
    const int lane = tid & 31, wid = tid >> 5;
    const int wm = wid >> 2, wn = wid & 3;

    // cp.async loader: thread -> (row = tid>>1, 4 segs starting at (tid&1)*4)
    const int lr = tid >> 1;
    const int ls0 = (tid & 1) << 2;
    const float* aSrc = A + (size_t)lr * K + (ls0 << 2);
    const float* bSrc = B + (size_t)lr * K + (ls0 << 2);
    uint32_t dstOff[4];
#pragma unroll
    for (int q = 0; q < 4; ++q)
        dstOff[q] = (uint32_t)lr * 128u + (uint32_t)(((ls0 + q) ^ (lr & 7)) << 4);

    // ldmatrix lane geometry: lane L supplies row L&7 of matrix L>>3
    const int Lm = lane & 7, Lmat = lane >> 3;
    const uint32_t h = (uint32_t)(Lmat >> 1);
    uint32_t rowA[4], rowB[2];
#pragma unroll
    for (int mf = 0; mf < 4; ++mf)
        rowA[mf] = (uint32_t)(wm * 64 + mf * 16 + ((Lmat & 1) << 3) + Lm);
#pragma unroll
    for (int pr = 0; pr < 2; ++pr)
        rowB[pr] = (uint32_t)(wn * 32 + pr * 16 + ((Lmat & 1) << 3) + Lm);

    const int nCk = K >> 5;

    // prologue: fill stages 0,1
#pragma unroll
    for (int pc = 0; pc < 2; ++pc) {
        uint32_t stA = smem + (uint32_t)pc * 32768u;
#pragma unroll
        for (int q = 0; q < 4; ++q) {
            cpa16(stA + dstOff[q], aSrc + pc * 32 + (q << 2));
            cpa16(stA + 16384u + dstOff[q], bSrc + pc * 32 + (q << 2));
        }
        CP_COMMIT;
    }

    for (int ck = 0; ck < nCk; ++ck) {
        CP_WAIT1;          // chunk ck resident
        __syncthreads();   // also frees stage (ck+2)%3 (mma'd at ck-1)

        const int nk = ck + 2;
        if (nk < nCk) {
            uint32_t stA = smem + (uint32_t)(nk % 3) * 32768u;
#pragma unroll
            for (int q = 0; q < 4; ++q) {
                cpa16(stA + dstOff[q], aSrc + nk * 32 + (q << 2));
                cpa16(stA + 16384u + dstOff[q], bSrc + nk * 32 + (q << 2));
            }
        }
        CP_COMMIT;         // (possibly empty) group keeps wait bookkeeping exact

        const uint32_t stA = smem + (uint32_t)(ck % 3) * 32768u;
        const uint32_t stB = stA + 16384u;
#pragma unroll
        for (int ks = 0; ks < 4; ++ks) {
            uint32_t af[4][4], bf[2][4];
            const uint32_t sg = (uint32_t)(ks << 1) | h;
#pragma unroll
            for (int mf = 0; mf < 4; ++mf)
                ldsm4(af[mf], stA + rowA[mf] * 128u + ((sg ^ (rowA[mf] & 7u)) << 4));
#pragma unroll
            for (int pr = 0; pr < 2; ++pr)
                ldsm4(bf[pr], stB + rowB[pr] * 128u + ((sg ^ (rowB[pr] & 7u)) << 4));
#pragma unroll
            for (int mf = 0; mf < 4; ++mf)
#pragma unroll
                for (int nf = 0; nf < 4; ++nf) {
                    uint32_t b2[2] = { bf[nf >> 1][nf & 1], bf[nf >> 1][(nf & 1) + 2] };
                    mma8(acc[mf][nf], af[mf], b2);
                }
        }
    }
}

// ===========================================================================
// prep kernels
// ===========================================================================
__global__ __launch_bounds__(256) void wround_g(const float* __restrict__ wg) {
    int j = (blockIdx.x * 256 + threadIdx.x) << 2;
    float4 v = *(const float4*)(wg + j);
    g_wT[j + 0] = __uint_as_float(f2tf(v.x));
    g_wT[j + 1] = __uint_as_float(f2tf(v.y));
    g_wT[j + 2] = __uint_as_float(f2tf(v.z));
    g_wT[j + 3] = __uint_as_float(f2tf(v.w));
}

__global__ __launch_bounds__(256) void dt_g(const float* __restrict__ Dg) {
    __shared__ float t[32][33];
    const int m0 = blockIdx.x << 5, n0 = blockIdx.y << 5;
    const int tx = threadIdx.x & 31, ty = threadIdx.x >> 5;
#pragma unroll
    for (int r = 0; r < 32; r += 8) {
        int m = m0 + tx, n = n0 + ty + r;
        t[ty + r][tx] = (m < IR) ? Dg[(size_t)n * IR + m] : 0.0f;
    }
    __syncthreads();
#pragma unroll
    for (int r = 0; r < 32; r += 8) {
        int m = m0 + ty + r, n = n0 + tx;
        if (m < IR) g_DT[(size_t)m * 512 + n] = __uint_as_float(f2tf(t[tx][ty + r]));
    }
}

// xT[l][(b*d+m)][i*d+u] = rna(x[b][i][off + u*d + m]); one (b,i) pair per warp
__global__ __launch_bounds__(256) void xt_g(const float* __restrict__ xg) {
    __shared__ float tile[8][441];
    const int l = blockIdx.y;
    const int d = 2 * l + 1, off = c_off[l], K = d << 6, dd = d * d;
    const int P = (blockIdx.x << 3) + (threadIdx.x >> 5);
    const int lane = threadIdx.x & 31;
    const int b = P >> 6, i = P & 63;
    float* tw = tile[threadIdx.x >> 5];

    const float* src = xg + (size_t)b * BSTRIDE + i * IR + off;
    for (int j = lane; j < dd; j += 32) tw[j] = src[j];
    __syncwarp();

    const float invd = c_invd[l];
    float* dst = g_xT + c_XT[l] + (size_t)(b * d) * K + i * d;
    for (int j = lane; j < dd; j += 32) {
        int m = (int)((float)j * invd + 0.01f);
        int u = j - m * d;
        dst[m * K + u] = __uint_as_float(f2tf(tw[u * d + m]));
    }
}

// ===========================================================================
// psi GEMM: psi[p,m] = (1/sqrt512) * sum_n wT[p,n] * DT[m,n]; epilogue
// scatters rna(psi) straight into psiT[l][(o*d+v)][(i*d+u)].
// ===========================================================================
__global__ __launch_bounds__(256, 2) void psi_g() {
    extern __shared__ float dsm[];
    const uint32_t smem = s2u(dsm);
    const int bx = blockIdx.x;
    const int tm = bx & 31, tn = bx >> 5;

    float acc[4][4][4] = {};
    gemm_core(g_wT + (size_t)tm * 128 * 512, g_DT + (size_t)tn * 128 * 512, 512, smem, acc);

    const int lane = threadIdx.x & 31, wid = threadIdx.x >> 5;
    const int wm = wid >> 2, wn = wid & 3;
    const int gid = lane >> 2, tig = lane & 3;
#pragma unroll
    for (int mf = 0; mf < 4; ++mf)
#pragma unroll
        for (int nf = 0; nf < 4; ++nf)
#pragma unroll
            for (int e = 0; e < 4; ++e) {
                int p = (tm << 7) + wm * 64 + mf * 16 + gid + ((e >> 1) << 3);
                int m = (tn << 7) + wn * 32 + nf * 8 + (tig << 1) + (e & 1);
                if (m < IR) {
                    int l = 0;
#pragma unroll
                    for (int j = 1; j < 11; ++j) l += (m >= c_off[j]);
                    int d = 2 * l + 1;
                    int r = m - c_off[l];
                    int u = (int)((float)r * c_invd[l] + 0.01f);
                    int v = r - u * d;
                    int i = p >> 6, o = p & 63;
                    g_psiT[c_PT[l] + (o * d + v) * (d << 6) + i * d + u] =
                        __uint_as_float(f2tf(acc[mf][nf][e] * SCALE_PSI));
                }
            }
}

// ===========================================================================
// so3 GEMM: per l, C[bm,ov] = alpha_l * sum_k xT[bm,k] * psiT[ov,k]
// M=256d (2d tiles), N=64d ((d+1)/2 tiles, last half-padded), K=64d.
// ===========================================================================
__global__ __launch_bounds__(256, 2) void so3_g(float* __restrict__ outg) {
    extern __shared__ float dsm[];
    const uint32_t smem = s2u(dsm);
    const int bx = 1891 - blockIdx.x;        // big-l tiles first
    int l = 0;
#pragma unroll
    for (int j = 1; j < 11; ++j) l += (bx >= c_tcum[j]);
    const int d = 2 * l + 1;
    const int K = d << 6;
    const int t = bx - c_tcum[l];
    const int tile_n = (int)((float)t * c_inv2d[l] + 0.01f);
    const int tile_m = t - tile_n * (d << 1);

    float acc[4][4][4] = {};
    gemm_core(g_xT + c_XT[l] + (size_t)tile_m * 128 * K,
              g_psiT + c_PT[l] + (size_t)tile_n * 128 * K, K, smem, acc);

    const float alpha = c_alpha[l];
    const float invd = c_invd[l];
    const int off = c_off[l];
    const int nValid = d << 6;
    const int lane = threadIdx.x & 31, wid = threadIdx.x >> 5;
    const int wm = wid >> 2, wn = wid & 3;
    const int gid = lane >> 2, tig = lane & 3;
#pragma unroll
    for (int mf = 0; mf < 4; ++mf)
#pragma unroll
        for (int nf = 0; nf < 4; ++nf)
#pragma unroll
            for (int e = 0; e < 4; ++e) {
                int ov = (tile_n << 7) + wn * 32 + nf * 8 + (tig << 1) + (e & 1);
                if (ov < nValid) {
                    int bm = (tile_m << 7) + wm * 64 + mf * 16 + gid + ((e >> 1) << 3);
                    int b = (int)((float)bm * invd + 0.01f);
                    int m = bm - b * d;
                    int o = (int)((float)ov * invd + 0.01f);
                    int v = ov - o * d;
                    outg[b * BSTRIDE + o * IR + off + v * d + m] = acc[mf][nf][e] * alpha;
                }
            }
}

// ---------------------------------------------------------------------------
extern "C" void kernel_launch(void* const* d_in, const int* in_sizes, int n_in,
                              void* d_out, int out_size) {
    const float *x = nullptr, *D = nullptr, *w = nullptr;
    for (int i = 0; i < n_in; ++i) {
        int s = in_sizes[i];
        if (s == 256 * 64 * IR) x = (const float*)d_in[i];
        else if (s == 512 * IR) D = (const float*)d_in[i];
        else if (s == 64 * 64 * 512) w = (const float*)d_in[i];
    }

    cudaFuncSetAttribute(psi_g, cudaFuncAttributeMaxDynamicSharedMemorySize, 98304);
    cudaFuncSetAttribute(so3_g, cudaFuncAttributeMaxDynamicSharedMemorySize, 98304);

    wround_g<<<2048, 256>>>(w);
    dt_g<<<dim3(56, 16), 256>>>(D);
    xt_g<<<dim3(2048, 11), 256>>>(x);
    psi_g<<<448, 256, 98304>>>();
    so3_g<<<1892, 256, 98304>>>((float*)d_out);
}

// round 6
// speedup vs baseline: 3.6158x; 1.2260x over previous
#include <cuda_runtime.h>
#include <cuda_fp16.h>
#include <cstdint>

#define IR 1771
#define BSTRIDE (64 * IR)
#define SCALE_PSI 0.04419417382415922f   // 1/sqrt(512)

// ---------------- device scratch (all zero-initialized .bss) ----------------
__device__ __half g_wT[64 * 64 * 512];    // rn-rounded w  [p=4096][k=512]
__device__ __half g_DT[1792 * 512];       // rn D^T [m(pad 1792)][n=512]
__device__ __half g_psiT[7344128];        // per-l [ov][k] (+pad rows, zero)
__device__ __half g_xT[29016064];         // per-l [bm][k]

__constant__ int c_off[11]  = {0, 1, 10, 35, 84, 165, 286, 455, 680, 969, 1330};
__constant__ int c_PT[11]   = {0, 8192, 45056, 147456, 348160, 679936, 1175552,
                               1867776, 2789376, 3973120, 5451776};
__constant__ int c_XT[11]   = {0, 16384, 163840, 573440, 1376256, 2703360, 4685824,
                               7454720, 11141120, 15876096, 21790720};
__constant__ int c_tcum[12] = {0, 2, 14, 44, 100, 190, 322, 504, 744, 1050, 1430, 1892};
__constant__ float c_invd[11]  = {1.0f, 1.0f/3.0f, 0.2f, 1.0f/7.0f, 1.0f/9.0f, 1.0f/11.0f,
                                  1.0f/13.0f, 1.0f/15.0f, 1.0f/17.0f, 1.0f/19.0f, 1.0f/21.0f};
__constant__ float c_inv2d[11] = {0.5f, 1.0f/6.0f, 0.1f, 1.0f/14.0f, 1.0f/18.0f, 1.0f/22.0f,
                                  1.0f/26.0f, 1.0f/30.0f, 1.0f/34.0f, 1.0f/38.0f, 1.0f/42.0f};
__constant__ float c_alpha[11] = {0.125f, 0.072168784f, 0.055901699f, 0.047245559f,
                                  0.041666667f, 0.037688918f, 0.034668700f, 0.032274861f,
                                  0.030316953f, 0.028676967f, 0.027277236f};

// ---------------------------------------------------------------- helpers
__device__ __forceinline__ uint32_t s2u(const void* p) {
    uint32_t a;
    asm("{ .reg .u64 t; cvta.to.shared.u64 t, %1; cvt.u32.u64 %0, t; }" : "=r"(a) : "l"(p));
    return a;
}
__device__ __forceinline__ void mma16(float* c, const uint32_t* a, const uint32_t* b) {
    asm volatile(
        "mma.sync.aligned.m16n8k16.row.col.f32.f16.f16.f32 "
        "{%0,%1,%2,%3}, {%4,%5,%6,%7}, {%8,%9}, {%0,%1,%2,%3};"
        : "+f"(c[0]), "+f"(c[1]), "+f"(c[2]), "+f"(c[3])
        : "r"(a[0]), "r"(a[1]), "r"(a[2]), "r"(a[3]), "r"(b[0]), "r"(b[1]));
}
__device__ __forceinline__ void ldsm4(uint32_t* r, uint32_t addr) {
    asm volatile("ldmatrix.sync.aligned.m8n8.x4.shared.b16 {%0,%1,%2,%3}, [%4];"
                 : "=r"(r[0]), "=r"(r[1]), "=r"(r[2]), "=r"(r[3]) : "r"(addr));
}
__device__ __forceinline__ void cpa16(uint32_t dst, const void* src) {
    asm volatile("cp.async.cg.shared.global [%0], [%1], 16;" :: "r"(dst), "l"(src));
}
#define CP_COMMIT asm volatile("cp.async.commit_group;" ::: "memory")
#define CP_WAIT1  asm volatile("cp.async.wait_group 1;" ::: "memory")

// ===========================================================================
// Dense fp16 GEMM core: C[128,128] += A[128,K] * B[128,K]^T (fp32 accum).
// 8 warps (2m x 4n), warp tile 64x32, K-chunk 64 (4 x k16 steps), 3-stage
// cp.async pipeline, ldmatrix.x4 fragments, XOR-swizzled 128B rows.
// ===========================================================================
__device__ __forceinline__ void gemm_core(const __half* __restrict__ A,
                                          const __half* __restrict__ B,
                                          int K, uint32_t smem,
                                          float (&acc)[4][4][4]) {
    const int tid = threadIdx.x;
    const int lane = tid & 31, wid = tid >> 5;
    const int wm = wid >> 2, wn = wid & 3;

    // cp.async loader: one 128B row per thread (A: tid<128, B: tid>=128)
    const int lr = tid & 127;
    const __half* src = ((tid >= 128) ? B : A) + (size_t)lr * K;
    const uint32_t dbase = ((tid >= 128) ? 16384u : 0u) + (uint32_t)lr * 128u;
    const uint32_t sx = (uint32_t)(lr & 7);

    // ldmatrix lane geometry: lane L supplies row L&7 of matrix L>>3
    const int Lm = lane & 7, Lmat = lane >> 3;
    const uint32_t h = (uint32_t)(Lmat >> 1);
    uint32_t rowA[4], rowB[2];
#pragma unroll
    for (int mf = 0; mf < 4; ++mf)
        rowA[mf] = (uint32_t)(wm * 64 + mf * 16 + ((Lmat & 1) << 3) + Lm);
#pragma unroll
    for (int pr = 0; pr < 2; ++pr)
        rowB[pr] = (uint32_t)(wn * 32 + pr * 16 + ((Lmat & 1) << 3) + Lm);

    const int nCk = K >> 6;

    // prologue: fill stages 0,1
#pragma unroll
    for (int pc = 0; pc < 2; ++pc) {
        uint32_t st = smem + (uint32_t)pc * 32768u;
#pragma unroll
        for (int q = 0; q < 8; ++q)
            cpa16(st + dbase + ((((uint32_t)q) ^ sx) << 4), src + pc * 64 + (q << 3));
        CP_COMMIT;
    }

    for (int ck = 0; ck < nCk; ++ck) {
        CP_WAIT1;          // chunk ck resident
        __syncthreads();   // all warps done with stage (ck+2)%3

        const int nk = ck + 2;
        if (nk < nCk) {
            uint32_t st = smem + (uint32_t)(nk % 3) * 32768u;
#pragma unroll
            for (int q = 0; q < 8; ++q)
                cpa16(st + dbase + ((((uint32_t)q) ^ sx) << 4), src + nk * 64 + (q << 3));
        }
        CP_COMMIT;         // (possibly empty) keeps wait bookkeeping exact

        const uint32_t stA = smem + (uint32_t)(ck % 3) * 32768u;
        const uint32_t stB = stA + 16384u;
#pragma unroll
        for (int ks = 0; ks < 4; ++ks) {
            uint32_t af[4][4], bf[2][4];
            const uint32_t sg = (uint32_t)(ks << 1) | h;
#pragma unroll
            for (int mf = 0; mf < 4; ++mf)
                ldsm4(af[mf], stA + rowA[mf] * 128u + ((sg ^ (rowA[mf] & 7u)) << 4));
#pragma unroll
            for (int pr = 0; pr < 2; ++pr)
                ldsm4(bf[pr], stB + rowB[pr] * 128u + ((sg ^ (rowB[pr] & 7u)) << 4));
#pragma unroll
            for (int mf = 0; mf < 4; ++mf)
#pragma unroll
                for (int nf = 0; nf < 4; ++nf) {
                    uint32_t b2[2] = { bf[nf >> 1][nf & 1], bf[nf >> 1][(nf & 1) + 2] };
                    mma16(acc[mf][nf], af[mf], b2);
                }
        }
    }
}

// ===========================================================================
// prep kernels
// ===========================================================================
__global__ __launch_bounds__(256) void wround_g(const float* __restrict__ wg) {
    int j = (blockIdx.x * 256 + threadIdx.x) << 2;
    float4 v = *(const float4*)(wg + j);
    g_wT[j + 0] = __float2half_rn(v.x);
    g_wT[j + 1] = __float2half_rn(v.y);
    g_wT[j + 2] = __float2half_rn(v.z);
    g_wT[j + 3] = __float2half_rn(v.w);
}

__global__ __launch_bounds__(256) void dt_g(const float* __restrict__ Dg) {
    __shared__ float t[32][33];
    const int m0 = blockIdx.x << 5, n0 = blockIdx.y << 5;
    const int tx = threadIdx.x & 31, ty = threadIdx.x >> 5;
#pragma unroll
    for (int r = 0; r < 32; r += 8) {
        int m = m0 + tx, n = n0 + ty + r;
        t[ty + r][tx] = (m < IR) ? Dg[(size_t)n * IR + m] : 0.0f;
    }
    __syncthreads();
#pragma unroll
    for (int r = 0; r < 32; r += 8) {
        int m = m0 + ty + r, n = n0 + tx;
        if (m < IR) g_DT[(size_t)m * 512 + n] = __float2half_rn(t[tx][ty + r]);
    }
}

// xT[l][(b*d+m)][i*d+u] = rn(x[b][i][off + u*d + m]); one (b,i) pair per warp
__global__ __launch_bounds__(256) void xt_g(const float* __restrict__ xg) {
    __shared__ float tile[8][441];
    const int l = blockIdx.y;
    const int d = 2 * l + 1, off = c_off[l], K = d << 6, dd = d * d;
    const int P = (blockIdx.x << 3) + (threadIdx.x >> 5);
    const int lane = threadIdx.x & 31;
    const int b = P >> 6, i = P & 63;
    float* tw = tile[threadIdx.x >> 5];

    const float* src = xg + (size_t)b * BSTRIDE + i * IR + off;
    for (int j = lane; j < dd; j += 32) tw[j] = src[j];
    __syncwarp();

    const float invd = c_invd[l];
    __half* dst = g_xT + c_XT[l] + (size_t)(b * d) * K + i * d;
    for (int j = lane; j < dd; j += 32) {
        int m = (int)((float)j * invd + 0.01f);
        int u = j - m * d;
        dst[m * K + u] = __float2half_rn(tw[u * d + m]);
    }
}

// ===========================================================================
// psi GEMM: psi[p,m] = (1/sqrt512) * sum_n wT[p,n] * DT[m,n]; epilogue
// scatters rn(psi) straight into psiT[l][(o*d+v)][(i*d+u)].
// ===========================================================================
__global__ __launch_bounds__(256, 2) void psi_g() {
    extern __shared__ float dsm[];
    const uint32_t smem = s2u(dsm);
    const int bx = blockIdx.x;
    const int tm = bx & 31, tn = bx >> 5;

    float acc[4][4][4] = {};
    gemm_core(g_wT + (size_t)tm * 128 * 512, g_DT + (size_t)tn * 128 * 512, 512, smem, acc);

    const int lane = threadIdx.x & 31, wid = threadIdx.x >> 5;
    const int wm = wid >> 2, wn = wid & 3;
    const int gid = lane >> 2, tig = lane & 3;
#pragma unroll
    for (int mf = 0; mf < 4; ++mf)
#pragma unroll
        for (int nf = 0; nf < 4; ++nf)
#pragma unroll
            for (int e = 0; e < 4; ++e) {
                int p = (tm << 7) + wm * 64 + mf * 16 + gid + ((e >> 1) << 3);
                int m = (tn << 7) + wn * 32 + nf * 8 + (tig << 1) + (e & 1);
                if (m < IR) {
                    int l = 0;
#pragma unroll
                    for (int j = 1; j < 11; ++j) l += (m >= c_off[j]);
                    int d = 2 * l + 1;
                    int r = m - c_off[l];
                    int u = (int)((float)r * c_invd[l] + 0.01f);
                    int v = r - u * d;
                    int i = p >> 6, o = p & 63;
                    g_psiT[c_PT[l] + (o * d + v) * (d << 6) + i * d + u] =
                        __float2half_rn(acc[mf][nf][e] * SCALE_PSI);
                }
            }
}

// ===========================================================================
// so3 GEMM: per l, C[bm,ov] = alpha_l * sum_k xT[bm,k] * psiT[ov,k]
// M=256d (2d tiles), N=64d ((d+1)/2 tiles, last half zero-padded), K=64d.
// ===========================================================================
__global__ __launch_bounds__(256, 2) void so3_g(float* __restrict__ outg) {
    extern __shared__ float dsm[];
    const uint32_t smem = s2u(dsm);
    const int bx = 1891 - blockIdx.x;        // big-l tiles first
    int l = 0;
#pragma unroll
    for (int j = 1; j < 11; ++j) l += (bx >= c_tcum[j]);
    const int d = 2 * l + 1;
    const int K = d << 6;
    const int t = bx - c_tcum[l];
    const int tile_n = (int)((float)t * c_inv2d[l] + 0.01f);
    const int tile_m = t - tile_n * (d << 1);

    float acc[4][4][4] = {};
    gemm_core(g_xT + c_XT[l] + (size_t)tile_m * 128 * K,
              g_psiT + c_PT[l] + (size_t)tile_n * 128 * K, K, smem, acc);

    const float alpha = c_alpha[l];
    const float invd = c_invd[l];
    const int off = c_off[l];
    const int nValid = d << 6;
    const int lane = threadIdx.x & 31, wid = threadIdx.x >> 5;
    const int wm = wid >> 2, wn = wid & 3;
    const int gid = lane >> 2, tig = lane & 3;
#pragma unroll
    for (int mf = 0; mf < 4; ++mf)
#pragma unroll
        for (int nf = 0; nf < 4; ++nf)
#pragma unroll
            for (int e = 0; e < 4; ++e) {
                int ov = (tile_n << 7) + wn * 32 + nf * 8 + (tig << 1) + (e & 1);
                if (ov < nValid) {
                    int bm = (tile_m << 7) + wm * 64 + mf * 16 + gid + ((e >> 1) << 3);
                    int b = (int)((float)bm * invd + 0.01f);
                    int m = bm - b * d;
                    int o = (int)((float)ov * invd + 0.01f);
                    int v = ov - o * d;
                    outg[b * BSTRIDE + o * IR + off + v * d + m] = acc[mf][nf][e] * alpha;
                }
            }
}

// ---------------------------------------------------------------------------
extern "C" void kernel_launch(void* const* d_in, const int* in_sizes, int n_in,
                              void* d_out, int out_size) {
    const float *x = nullptr, *D = nullptr, *w = nullptr;
    for (int i = 0; i < n_in; ++i) {
        int s = in_sizes[i];
        if (s == 256 * 64 * IR) x = (const float*)d_in[i];
        else if (s == 512 * IR) D = (const float*)d_in[i];
        else if (s == 64 * 64 * 512) w = (const float*)d_in[i];
    }

    cudaFuncSetAttribute(psi_g, cudaFuncAttributeMaxDynamicSharedMemorySize, 98304);
    cudaFuncSetAttribute(so3_g, cudaFuncAttributeMaxDynamicSharedMemorySize, 98304);

    wround_g<<<2048, 256>>>(w);
    dt_g<<<dim3(56, 16), 256>>>(D);
    xt_g<<<dim3(2048, 11), 256>>>(x);
    psi_g<<<448, 256, 98304>>>();
    so3_g<<<1892, 256, 98304>>>((float*)d_out);
}

// round 7
// speedup vs baseline: 4.6434x; 1.2842x over previous
#include <cuda_runtime.h>
#include <cuda_fp16.h>
#include <cstdint>

#define IR 1771
#define BSTRIDE (64 * IR)
#define SCALE_PSI 0.04419417382415922f   // 1/sqrt(512)

// ---------------- device scratch (all zero-initialized .bss) ----------------
__device__ __half g_wT[64 * 64 * 512];    // rn-rounded w  [p=4096][k=512]
__device__ __half g_DT[1792 * 512];       // rn D^T [m(pad 1792)][n=512]
__device__ __half g_psiT[7344128];        // per-l [ov][k] (+pad rows, zero)
__device__ __half g_xT[29016064];         // per-l [bm][k]

__constant__ int c_off[11]  = {0, 1, 10, 35, 84, 165, 286, 455, 680, 969, 1330};
__constant__ int c_PT[11]   = {0, 8192, 45056, 147456, 348160, 679936, 1175552,
                               1867776, 2789376, 3973120, 5451776};
__constant__ int c_XT[11]   = {0, 16384, 163840, 573440, 1376256, 2703360, 4685824,
                               7454720, 11141120, 15876096, 21790720};
// cumulative d*ceil(d/2) block counts (946 total)
__constant__ int c_tB[12]   = {0, 1, 7, 22, 50, 95, 161, 252, 372, 525, 715, 946};
__constant__ float c_invd[11]  = {1.0f, 1.0f/3.0f, 0.2f, 1.0f/7.0f, 1.0f/9.0f, 1.0f/11.0f,
                                  1.0f/13.0f, 1.0f/15.0f, 1.0f/17.0f, 1.0f/19.0f, 1.0f/21.0f};
__constant__ float c_alpha[11] = {0.125f, 0.072168784f, 0.055901699f, 0.047245559f,
                                  0.041666667f, 0.037688918f, 0.034668700f, 0.032274861f,
                                  0.030316953f, 0.028676967f, 0.027277236f};

// ---------------------------------------------------------------- helpers
__device__ __forceinline__ uint32_t s2u(const void* p) {
    uint32_t a;
    asm("{ .reg .u64 t; cvta.to.shared.u64 t, %1; cvt.u32.u64 %0, t; }" : "=r"(a) : "l"(p));
    return a;
}
__device__ __forceinline__ void mma16(float* c, const uint32_t* a, const uint32_t* b) {
    asm volatile(
        "mma.sync.aligned.m16n8k16.row.col.f32.f16.f16.f32 "
        "{%0,%1,%2,%3}, {%4,%5,%6,%7}, {%8,%9}, {%0,%1,%2,%3};"
        : "+f"(c[0]), "+f"(c[1]), "+f"(c[2]), "+f"(c[3])
        : "r"(a[0]), "r"(a[1]), "r"(a[2]), "r"(a[3]), "r"(b[0]), "r"(b[1]));
}
__device__ __forceinline__ void ldsm4(uint32_t* r, uint32_t addr) {
    asm volatile("ldmatrix.sync.aligned.m8n8.x4.shared.b16 {%0,%1,%2,%3}, [%4];"
                 : "=r"(r[0]), "=r"(r[1]), "=r"(r[2]), "=r"(r[3]) : "r"(addr));
}
__device__ __forceinline__ void cpa16(uint32_t dst, const void* src) {
    asm volatile("cp.async.cg.shared.global [%0], [%1], 16;" :: "r"(dst), "l"(src));
}
#define CP_COMMIT asm volatile("cp.async.commit_group;" ::: "memory")
#define CP_WAIT2  asm volatile("cp.async.wait_group 2;" ::: "memory")

#define STAGE_B 49152u          // 32KB A (256 rows) + 16KB B (128 rows)
#define SMEM_TOTAL (4u * STAGE_B)

// ===========================================================================
// Dense fp16 GEMM core: C[256,128] += A[256,K] * B[128,K]^T (fp32 accum).
// 8 warps (4m x 2n), warp tile 64x64, K-chunk 64 (4 x k16), 4-stage cp.async
// pipeline (wait_group 2), ldmatrix.x4 fragments, XOR-swizzled 128B rows.
// ===========================================================================
__device__ __forceinline__ void gemm_core(const __half* __restrict__ A,
                                          const __half* __restrict__ B,
                                          int K, uint32_t smem,
                                          float (&acc)[4][8][4]) {
    const int tid = threadIdx.x;
    const int lane = tid & 31, wid = tid >> 5;
    const int wm = wid >> 1, wn = wid & 1;

    // loader: seg s = tid&7, base row rb = tid>>3 (0..31); rows rb+32q:
    //   q 0..7  -> A rows rb+32q   (stage rows 0..255)
    //   q 8..11 -> B rows rb+32(q-8) (stage rows 256..383)
    const int s = tid & 7, rb = tid >> 3;
    const __half* srcA = A + (size_t)rb * K + (s << 3);
    const __half* srcB = B + (size_t)rb * K + (s << 3);
    const uint32_t swz = ((uint32_t)(s ^ (rb & 7))) << 4;
    uint32_t dstOff[12];
#pragma unroll
    for (int q = 0; q < 12; ++q)
        dstOff[q] = (uint32_t)(rb + (q << 5)) * 128u + swz;

    // ldmatrix lane geometry: lane L supplies row L&7 of matrix L>>3
    const int Lm = lane & 7, Lmat = lane >> 3;
    const uint32_t h = (uint32_t)(Lmat >> 1);
    uint32_t rowA[4], rowB[4];
#pragma unroll
    for (int mf = 0; mf < 4; ++mf)
        rowA[mf] = (uint32_t)(wm * 64 + mf * 16 + ((Lmat & 1) << 3) + Lm);
#pragma unroll
    for (int pr = 0; pr < 4; ++pr)
        rowB[pr] = (uint32_t)(wn * 64 + pr * 16 + ((Lmat & 1) << 3) + Lm);

    const int nCk = K >> 6;

    // prologue: fill stages 0..2
#pragma unroll
    for (int pc = 0; pc < 3; ++pc) {
        uint32_t st = smem + (uint32_t)pc * STAGE_B;
#pragma unroll
        for (int q = 0; q < 8; ++q)
            cpa16(st + dstOff[q], srcA + (size_t)(q << 5) * K + pc * 64);
#pragma unroll
        for (int q = 8; q < 12; ++q)
            cpa16(st + dstOff[q], srcB + (size_t)((q - 8) << 5) * K + pc * 64);
        CP_COMMIT;
    }

    for (int ck = 0; ck < nCk; ++ck) {
        CP_WAIT2;          // chunk ck resident
        __syncthreads();   // all warps done with stage (ck+3)%4

        const int nk = ck + 3;
        if (nk < nCk) {
            uint32_t st = smem + (uint32_t)(nk & 3) * STAGE_B;
#pragma unroll
            for (int q = 0; q < 8; ++q)
                cpa16(st + dstOff[q], srcA + (size_t)(q << 5) * K + nk * 64);
#pragma unroll
            for (int q = 8; q < 12; ++q)
                cpa16(st + dstOff[q], srcB + (size_t)((q - 8) << 5) * K + nk * 64);
        }
        CP_COMMIT;         // (possibly empty) keeps wait bookkeeping exact

        const uint32_t stA = smem + (uint32_t)(ck & 3) * STAGE_B;
        const uint32_t stB = stA + 32768u;
#pragma unroll
        for (int ks = 0; ks < 4; ++ks) {
            uint32_t af[4][4], bf[4][4];
            const uint32_t sg = (uint32_t)(ks << 1) | h;
#pragma unroll
            for (int mf = 0; mf < 4; ++mf)
                ldsm4(af[mf], stA + rowA[mf] * 128u + ((sg ^ (rowA[mf] & 7u)) << 4));
#pragma unroll
            for (int pr = 0; pr < 4; ++pr)
                ldsm4(bf[pr], stB + rowB[pr] * 128u + ((sg ^ (rowB[pr] & 7u)) << 4));
#pragma unroll
            for (int mf = 0; mf < 4; ++mf)
#pragma unroll
                for (int nf = 0; nf < 8; ++nf) {
                    uint32_t b2[2] = { bf[nf >> 1][nf & 1], bf[nf >> 1][(nf & 1) + 2] };
                    mma16(acc[mf][nf], af[mf], b2);
                }
        }
    }
}

// ===========================================================================
// prep kernels
// ===========================================================================
__global__ __launch_bounds__(256) void wround_g(const float* __restrict__ wg) {
    int j = (blockIdx.x * 256 + threadIdx.x) << 2;
    float4 v = *(const float4*)(wg + j);
    g_wT[j + 0] = __float2half_rn(v.x);
    g_wT[j + 1] = __float2half_rn(v.y);
    g_wT[j + 2] = __float2half_rn(v.z);
    g_wT[j + 3] = __float2half_rn(v.w);
}

__global__ __launch_bounds__(256) void dt_g(const float* __restrict__ Dg) {
    __shared__ float t[32][33];
    const int m0 = blockIdx.x << 5, n0 = blockIdx.y << 5;
    const int tx = threadIdx.x & 31, ty = threadIdx.x >> 5;
#pragma unroll
    for (int r = 0; r < 32; r += 8) {
        int m = m0 + tx, n = n0 + ty + r;
        t[ty + r][tx] = (m < IR) ? Dg[(size_t)n * IR + m] : 0.0f;
    }
    __syncthreads();
#pragma unroll
    for (int r = 0; r < 32; r += 8) {
        int m = m0 + ty + r, n = n0 + tx;
        if (m < IR) g_DT[(size_t)m * 512 + n] = __float2half_rn(t[tx][ty + r]);
    }
}

// xT[l][(b*d+m)][i*d+u] = rn(x[b][i][off + u*d + m]); one (b,i) pair per warp
__global__ __launch_bounds__(256) void xt_g(const float* __restrict__ xg) {
    __shared__ float tile[8][441];
    const int l = blockIdx.y;
    const int d = 2 * l + 1, off = c_off[l], K = d << 6, dd = d * d;
    const int P = (blockIdx.x << 3) + (threadIdx.x >> 5);
    const int lane = threadIdx.x & 31;
    const int b = P >> 6, i = P & 63;
    float* tw = tile[threadIdx.x >> 5];

    const float* src = xg + (size_t)b * BSTRIDE + i * IR + off;
    for (int j = lane; j < dd; j += 32) tw[j] = src[j];
    __syncwarp();

    const float invd = c_invd[l];
    __half* dst = g_xT + c_XT[l] + (size_t)(b * d) * K + i * d;
    for (int j = lane; j < dd; j += 32) {
        int m = (int)((float)j * invd + 0.01f);
        int u = j - m * d;
        dst[m * K + u] = __float2half_rn(tw[u * d + m]);
    }
}

// ===========================================================================
// psi GEMM: psi[p,m] = (1/sqrt512) * sum_n wT[p,n] * DT[m,n]; epilogue
// scatters rn(psi) straight into psiT[l][(o*d+v)][(i*d+u)].
// Grid: 16 tm (p/256) x 14 tn (m/128).
// ===========================================================================
__global__ __launch_bounds__(256, 1) void psi_g() {
    extern __shared__ float dsm[];
    const uint32_t smem = s2u(dsm);
    const int tm = blockIdx.x & 15, tn = blockIdx.x >> 4;

    float acc[4][8][4] = {};
    gemm_core(g_wT + (size_t)tm * 256 * 512, g_DT + (size_t)tn * 128 * 512, 512, smem, acc);

    const int lane = threadIdx.x & 31, wid = threadIdx.x >> 5;
    const int wm = wid >> 1, wn = wid & 1;
    const int gid = lane >> 2, tig = lane & 3;
#pragma unroll
    for (int mf = 0; mf < 4; ++mf)
#pragma unroll
        for (int nf = 0; nf < 8; ++nf)
#pragma unroll
            for (int e = 0; e < 4; ++e) {
                int p = (tm << 8) + wm * 64 + mf * 16 + gid + ((e >> 1) << 3);
                int m = (tn << 7) + wn * 64 + nf * 8 + (tig << 1) + (e & 1);
                if (m < IR) {
                    int l = 0;
#pragma unroll
                    for (int j = 1; j < 11; ++j) l += (m >= c_off[j]);
                    int d = 2 * l + 1;
                    int r = m - c_off[l];
                    int u = (int)((float)r * c_invd[l] + 0.01f);
                    int v = r - u * d;
                    int i = p >> 6, o = p & 63;
                    g_psiT[c_PT[l] + (o * d + v) * (d << 6) + i * d + u] =
                        __float2half_rn(acc[mf][nf][e] * SCALE_PSI);
                }
            }
}

// ===========================================================================
// so3 GEMM: per l, C[bm,ov] = alpha_l * sum_k xT[bm,k] * psiT[ov,k]
// Block tile M=256 (bm, exact), N=128 (ov, last tile zero-padded), K=64d.
// d * ceil(d/2) tiles per l -> 946 blocks, big-l first.
// ===========================================================================
__global__ __launch_bounds__(256, 1) void so3_g(float* __restrict__ outg) {
    extern __shared__ float dsm[];
    const uint32_t smem = s2u(dsm);
    const int idx = 945 - blockIdx.x;        // big-l tiles first
    int l = 0;
#pragma unroll
    for (int j = 1; j < 11; ++j) l += (idx >= c_tB[j]);
    const int d = 2 * l + 1;
    const int K = d << 6;
    const int t = idx - c_tB[l];
    const int tile_n = (int)((float)t * c_invd[l] + 0.01f);  // t / d
    const int tile_m = t - tile_n * d;

    float acc[4][8][4] = {};
    gemm_core(g_xT + c_XT[l] + (size_t)tile_m * 256 * K,
              g_psiT + c_PT[l] + (size_t)tile_n * 128 * K, K, smem, acc);

    const float alpha = c_alpha[l];
    const float invd = c_invd[l];
    const int off = c_off[l];
    const int nValid = d << 6;
    const int lane = threadIdx.x & 31, wid = threadIdx.x >> 5;
    const int wm = wid >> 1, wn = wid & 1;
    const int gid = lane >> 2, tig = lane & 3;
#pragma unroll
    for (int mf = 0; mf < 4; ++mf)
#pragma unroll
        for (int nf = 0; nf < 8; ++nf)
#pragma unroll
            for (int e = 0; e < 4; ++e) {
                int ov = (tile_n << 7) + wn * 64 + nf * 8 + (tig << 1) + (e & 1);
                if (ov < nValid) {
                    int bm = (tile_m << 8) + wm * 64 + mf * 16 + gid + ((e >> 1) << 3);
                    int b = (int)((float)bm * invd + 0.01f);
                    int m = bm - b * d;
                    int o = (int)((float)ov * invd + 0.01f);
                    int v = ov - o * d;
                    outg[b * BSTRIDE + o * IR + off + v * d + m] = acc[mf][nf][e] * alpha;
                }
            }
}

// ---------------------------------------------------------------------------
extern "C" void kernel_launch(void* const* d_in, const int* in_sizes, int n_in,
                              void* d_out, int out_size) {
    const float *x = nullptr, *D = nullptr, *w = nullptr;
    for (int i = 0; i < n_in; ++i) {
        int s = in_sizes[i];
        if (s == 256 * 64 * IR) x = (const float*)d_in[i];
        else if (s == 512 * IR) D = (const float*)d_in[i];
        else if (s == 64 * 64 * 512) w = (const float*)d_in[i];
    }

    cudaFuncSetAttribute(psi_g, cudaFuncAttributeMaxDynamicSharedMemorySize, SMEM_TOTAL);
    cudaFuncSetAttribute(so3_g, cudaFuncAttributeMaxDynamicSharedMemorySize, SMEM_TOTAL);

    wround_g<<<2048, 256>>>(w);
    dt_g<<<dim3(56, 16), 256>>>(D);
    xt_g<<<dim3(2048, 11), 256>>>(x);
    psi_g<<<224, 256, SMEM_TOTAL>>>();
    so3_g<<<946, 256, SMEM_TOTAL>>>((float*)d_out);
}